// round 11
// baseline (speedup 1.0000x reference)
#include <cuda_runtime.h>
#include <cstdint>

// Shapes fixed by problem: N=1024 nodes, D=256 feat, H=256 hidden.
#define NN 1024
#define DD 256
#define HH 256
#define NBLK 128          // <= 148 SMs, 1 CTA/SM -> all co-resident -> device barrier safe
#define NTHR 512          // 16 warps/block

// Scratch (__device__ globals: allocation-free rule)
__device__ float g_p[DD];     // w1[:D] @ w2
__device__ float g_q[DD];     // w1[D:] @ w2
__device__ float g_c;         // b1.w2 + b2
__device__ float g_eu[NN];    // exp(-(u_i + c))
__device__ float g_ev[NN];    // exp(-v_i)
__device__ float g_s[NN];     // eu_i * ev_i

// Monotonic arrival counter (never reset -> graph-replay safe) + epoch base.
__device__ unsigned g_ctr  = 0;
__device__ unsigned g_base = 0;   // advanced by 2*NBLK per launch by block 0

__device__ __forceinline__ float warp_reduce(float v) {
#pragma unroll
    for (int o = 16; o > 0; o >>= 1) v += __shfl_xor_sync(0xffffffffu, v, o);
    return v;
}

__device__ __forceinline__ float frcp(float x) {
    float y;
    asm("rcp.approx.f32 %0, %1;" : "=f"(y) : "f"(x));
    return y;
}

__device__ __forceinline__ unsigned ld_relaxed(const unsigned* p) {
    unsigned v;
    asm volatile("ld.relaxed.gpu.global.u32 %0, [%1];" : "=r"(v) : "l"(p) : "memory");
    return v;
}
__device__ __forceinline__ void st_relaxed(unsigned* p, unsigned v) {
    asm volatile("st.relaxed.gpu.global.u32 [%0], %1;" :: "l"(p), "r"(v) : "memory");
}
__device__ __forceinline__ void red_add_release(unsigned* p, unsigned a) {
    asm volatile("red.release.gpu.global.add.u32 [%0], %1;" :: "l"(p), "r"(a) : "memory");
}
__device__ __forceinline__ void fence_acq_rel() {
    asm volatile("fence.acq_rel.gpu;" ::: "memory");
}

// Grid barrier on a monotonic counter: fire-and-forget red.release arrival,
// pipelined relaxed polling, acq_rel fence on exit. (Proven in R10.)
__device__ __forceinline__ void grid_barrier(unsigned target) {
    __syncthreads();
    if (threadIdx.x == 0) {
        red_add_release(&g_ctr, 1u);
        unsigned v;
        do {
            unsigned a = ld_relaxed(&g_ctr);
            unsigned b = ld_relaxed(&g_ctr);
            unsigned c = ld_relaxed(&g_ctr);
            unsigned d = ld_relaxed(&g_ctr);
            v = a > b ? a : b;
            unsigned w = c > d ? c : d;
            v = v > w ? v : w;
        } while ((int)(v - target) < 0);      // wrap-safe monotonic compare
        fence_acq_rel();
    }
    __syncthreads();
}

__global__ void __launch_bounds__(NTHR, 1)
fused_decoder(const float* __restrict__ z,  const float* __restrict__ w1,
              const float* __restrict__ b1, const float* __restrict__ w2,
              const float* __restrict__ b2, float* __restrict__ out) {
    const int lane = threadIdx.x & 31;
    const int wid  = threadIdx.x >> 5;                        // 0..15

    // Warp roles (disjoint -> A-loads and z-prefetch issue concurrently at t=0):
    //   wid 0..7  : B-warps, node = blockIdx*8 + wid       (8 nodes per CTA)
    //   wid 8..11 : A-warps, row  = blockIdx*4 + (wid-8)   (4 w1-rows per CTA)
    //   wid 12 (block 0 only): c = b1.w2 + b2
    const bool isB = (wid < 8);
    const bool isA = (wid >= 8) && (wid < 12);
    const bool isC = (wid == 12) && (blockIdx.x == 0);
    const int  bnode = blockIdx.x * 8 + wid;                  // valid when isB
    const int  arow  = blockIdx.x * 4 + (wid - 8);            // valid when isA

    const unsigned base = ld_relaxed(&g_base);

    // ---- B-warps: prefetch this node's z row immediately ----
    float4 z0 = make_float4(0.f, 0.f, 0.f, 0.f);
    float4 z1 = z0;
    if (isB) {
        const float4* zrow = reinterpret_cast<const float4*>(z + (size_t)bnode * DD);
        z0 = zrow[lane];
        z1 = zrow[lane + 32];
    }

    // ---- A-warps (+c-warp): p = w1_top@w2, q = w1_bot@w2, c = b1.w2 + b2 ----
    if (isA || isC) {
        const float4* w2v = reinterpret_cast<const float4*>(w2);
        const float4* row = isA
            ? reinterpret_cast<const float4*>(w1 + (size_t)arow * HH)
            : reinterpret_cast<const float4*>(b1);
        float4 r0 = row[lane];
        float4 r1 = row[lane + 32];
        float4 a0 = w2v[lane];
        float4 a1 = w2v[lane + 32];
        float acc = r0.x * a0.x;
        acc = fmaf(r0.y, a0.y, acc);
        acc = fmaf(r0.z, a0.z, acc);
        acc = fmaf(r0.w, a0.w, acc);
        acc = fmaf(r1.x, a1.x, acc);
        acc = fmaf(r1.y, a1.y, acc);
        acc = fmaf(r1.z, a1.z, acc);
        acc = fmaf(r1.w, a1.w, acc);
        acc = warp_reduce(acc);
        if (lane == 0) {
            if (isC)              g_c = acc + b2[0];
            else if (arow < DD)   g_p[arow] = acc;
            else                  g_q[arow - DD] = acc;
        }
    }

    grid_barrier(base + NBLK);

    // ---- B-warps: eu = exp(-(z.p + c)), ev = exp(-(z.q)), s = eu*ev ----
    if (isB) {
        const float4* pv = reinterpret_cast<const float4*>(g_p);
        const float4* qv = reinterpret_cast<const float4*>(g_q);
        const float c = g_c;
        float4 p0 = pv[lane], p1 = pv[lane + 32];
        float4 q0 = qv[lane], q1 = qv[lane + 32];
        float su = z0.x * p0.x;
        su = fmaf(z0.y, p0.y, su);
        su = fmaf(z0.z, p0.z, su);
        su = fmaf(z0.w, p0.w, su);
        su = fmaf(z1.x, p1.x, su);
        su = fmaf(z1.y, p1.y, su);
        su = fmaf(z1.z, p1.z, su);
        su = fmaf(z1.w, p1.w, su);
        float sv = z0.x * q0.x;
        sv = fmaf(z0.y, q0.y, sv);
        sv = fmaf(z0.z, q0.z, sv);
        sv = fmaf(z0.w, q0.w, sv);
        sv = fmaf(z1.x, q1.x, sv);
        sv = fmaf(z1.y, q1.y, sv);
        sv = fmaf(z1.z, q1.z, sv);
        sv = fmaf(z1.w, q1.w, sv);
        su = warp_reduce(su);
        sv = warp_reduce(sv);
        if (lane == 0) {
            float eu = __expf(-(su + c));
            float ev = __expf(-sv);
            g_eu[bnode] = eu;
            g_ev[bnode] = ev;
            g_s[bnode]  = eu * ev;
        }
    }

    grid_barrier(base + 2u * NBLK);

    // ---- Phase C: adj[i,j] = (0.5*B + 0.5) / (B + s_i*s_j),
    //      B = 1 + eu_i*ev_j + eu_j*ev_i ----
    // CTA covers rows [8b, 8b+8). Thread handles rows row_sub*4..row_sub*4+3
    // (contiguous -> one float4 per row-side array) x 1 float4 column group.
    const int colg    = threadIdx.x & 255;      // float4 column group 0..255
    const int row_sub = threadIdx.x >> 8;       // 0..1
    const int rbase   = blockIdx.x * 8 + row_sub * 4;
    const float4 euj = reinterpret_cast<const float4*>(g_eu)[colg];
    const float4 evj = reinterpret_cast<const float4*>(g_ev)[colg];
    const float4 sj  = reinterpret_cast<const float4*>(g_s)[colg];
    const float4 eur = *reinterpret_cast<const float4*>(g_eu + rbase);
    const float4 evr = *reinterpret_cast<const float4*>(g_ev + rbase);
    const float4 sr  = *reinterpret_cast<const float4*>(g_s  + rbase);
    const float eua[4] = {eur.x, eur.y, eur.z, eur.w};
    const float eva[4] = {evr.x, evr.y, evr.z, evr.w};
    const float sa[4]  = {sr.x,  sr.y,  sr.z,  sr.w};
#pragma unroll
    for (int rr = 0; rr < 4; rr++) {
        const int i = rbase + rr;
        const float eui = eua[rr];
        const float evi = eva[rr];
        const float si  = sa[rr];
        float4 o;
        {
            float B = fmaf(euj.x, evi, fmaf(eui, evj.x, 1.f));
            o.x = fmaf(0.5f, B, 0.5f) * frcp(fmaf(si, sj.x, B));
        }
        {
            float B = fmaf(euj.y, evi, fmaf(eui, evj.y, 1.f));
            o.y = fmaf(0.5f, B, 0.5f) * frcp(fmaf(si, sj.y, B));
        }
        {
            float B = fmaf(euj.z, evi, fmaf(eui, evj.z, 1.f));
            o.z = fmaf(0.5f, B, 0.5f) * frcp(fmaf(si, sj.z, B));
        }
        {
            float B = fmaf(euj.w, evi, fmaf(eui, evj.w, 1.f));
            o.w = fmaf(0.5f, B, 0.5f) * frcp(fmaf(si, sj.w, B));
        }
        reinterpret_cast<float4*>(out)[(size_t)i * (NN / 4) + colg] = o;
    }

    // Advance epoch base for the next launch (causally after every CTA's entry
    // read of g_base, since barrier 2 has completed).
    if (blockIdx.x == 0 && threadIdx.x == 0) st_relaxed(&g_base, base + 2u * NBLK);
}

extern "C" void kernel_launch(void* const* d_in, const int* in_sizes, int n_in,
                              void* d_out, int out_size) {
    const float* z  = (const float*)d_in[0];  // [N, D]
    const float* w1 = (const float*)d_in[1];  // [2D, H]
    const float* b1 = (const float*)d_in[2];  // [H]
    const float* w2 = (const float*)d_in[3];  // [H]
    const float* b2 = (const float*)d_in[4];  // [1]
    float* out = (float*)d_out;               // [N, N]

    fused_decoder<<<NBLK, NTHR>>>(z, w1, b1, w2, b2, out);
}

// round 12
// speedup vs baseline: 1.0030x; 1.0030x over previous
#include <cuda_runtime.h>
#include <cstdint>

// Shapes fixed by problem: N=1024 nodes, D=256 feat, H=256 hidden.
#define NN 1024
#define DD 256
#define HH 256
#define NBLK 128          // <= 148 SMs, 1 CTA/SM -> all co-resident -> device barrier safe
#define NTHR 512          // 16 warps/block

// Scratch (__device__ globals: allocation-free rule)
__device__ float g_p[DD];     // w1[:D] @ w2
__device__ float g_q[DD];     // w1[D:] @ w2
__device__ float g_c;         // b1.w2 + b2
__device__ float g_eu[NN];    // exp(-(u_i + c))
__device__ float g_ev[NN];    // exp(-v_i)
__device__ float g_s[NN];     // eu_i * ev_i

// Monotonic arrival counter (never reset -> graph-replay safe) + epoch base.
__device__ unsigned g_ctr  = 0;
__device__ unsigned g_base = 0;   // advanced by 2*NBLK per launch by block 0

__device__ __forceinline__ float warp_reduce(float v) {
#pragma unroll
    for (int o = 16; o > 0; o >>= 1) v += __shfl_xor_sync(0xffffffffu, v, o);
    return v;
}

__device__ __forceinline__ float frcp(float x) {
    float y;
    asm("rcp.approx.f32 %0, %1;" : "=f"(y) : "f"(x));
    return y;
}

__device__ __forceinline__ unsigned ld_relaxed(const unsigned* p) {
    unsigned v;
    asm volatile("ld.relaxed.gpu.global.u32 %0, [%1];" : "=r"(v) : "l"(p) : "memory");
    return v;
}
__device__ __forceinline__ void st_relaxed(unsigned* p, unsigned v) {
    asm volatile("st.relaxed.gpu.global.u32 [%0], %1;" :: "l"(p), "r"(v) : "memory");
}
__device__ __forceinline__ void red_add_release(unsigned* p, unsigned a) {
    asm volatile("red.release.gpu.global.add.u32 [%0], %1;" :: "l"(p), "r"(a) : "memory");
}
__device__ __forceinline__ void fence_acq_rel() {
    asm volatile("fence.acq_rel.gpu;" ::: "memory");
}
__device__ __forceinline__ void st_cs_v4(float4* p, float4 v) {
    asm volatile("st.global.cs.v4.f32 [%0], {%1,%2,%3,%4};"
                 :: "l"(p), "f"(v.x), "f"(v.y), "f"(v.z), "f"(v.w) : "memory");
}

// Grid barrier on a monotonic counter: fire-and-forget red.release arrival,
// 8-deep pipelined relaxed polling, acq_rel fence on exit. (Proven in R10.)
__device__ __forceinline__ void grid_barrier(unsigned target) {
    __syncthreads();
    if (threadIdx.x == 0) {
        red_add_release(&g_ctr, 1u);
        unsigned v;
        do {
            unsigned a = ld_relaxed(&g_ctr);
            unsigned b = ld_relaxed(&g_ctr);
            unsigned c = ld_relaxed(&g_ctr);
            unsigned d = ld_relaxed(&g_ctr);
            unsigned e = ld_relaxed(&g_ctr);
            unsigned f = ld_relaxed(&g_ctr);
            unsigned g = ld_relaxed(&g_ctr);
            unsigned h = ld_relaxed(&g_ctr);
            unsigned m0 = a > b ? a : b;
            unsigned m1 = c > d ? c : d;
            unsigned m2 = e > f ? e : f;
            unsigned m3 = g > h ? g : h;
            m0 = m0 > m1 ? m0 : m1;
            m2 = m2 > m3 ? m2 : m3;
            v = m0 > m2 ? m0 : m2;
        } while ((int)(v - target) < 0);      // wrap-safe monotonic compare
        fence_acq_rel();
    }
    __syncthreads();
}

__global__ void __launch_bounds__(NTHR, 1)
fused_decoder(const float* __restrict__ z,  const float* __restrict__ w1,
              const float* __restrict__ b1, const float* __restrict__ w2,
              const float* __restrict__ b2, float* __restrict__ out) {
    const int lane  = threadIdx.x & 31;
    const int wid   = threadIdx.x >> 5;                       // 0..15
    const int gwarp = blockIdx.x * (NTHR / 32) + wid;         // 0..2047

    const unsigned base = ld_relaxed(&g_base);

    // ---- Phase A loads FIRST (they gate the dependency chain) ----
    const float4* w2v = reinterpret_cast<const float4*>(w2);
    float4 a0, a1, r0, r1;
    const bool doA = (gwarp <= 2 * DD);
    if (doA) {
        const float4* row = (gwarp < 2 * DD)
            ? reinterpret_cast<const float4*>(w1 + (size_t)gwarp * HH)
            : reinterpret_cast<const float4*>(b1);
        r0 = row[lane];
        r1 = row[lane + 32];
        a0 = w2v[lane];
        a1 = w2v[lane + 32];
    }

    // ---- Prefetch phase-B inputs (z row): latency overlaps phase A + barrier ----
    float4 z0 = make_float4(0.f, 0.f, 0.f, 0.f);
    float4 z1 = z0;
    if (gwarp < NN) {
        const float4* zrow = reinterpret_cast<const float4*>(z + (size_t)gwarp * DD);
        z0 = zrow[lane];
        z1 = zrow[lane + 32];
    }

    // ---- Phase A compute: p = w1_top@w2, q = w1_bot@w2, c = b1.w2 + b2 ----
    if (doA) {
        float acc = r0.x * a0.x;
        acc = fmaf(r0.y, a0.y, acc);
        acc = fmaf(r0.z, a0.z, acc);
        acc = fmaf(r0.w, a0.w, acc);
        acc = fmaf(r1.x, a1.x, acc);
        acc = fmaf(r1.y, a1.y, acc);
        acc = fmaf(r1.z, a1.z, acc);
        acc = fmaf(r1.w, a1.w, acc);
        acc = warp_reduce(acc);
        if (lane == 0) {
            if (gwarp < DD)           g_p[gwarp] = acc;
            else if (gwarp < 2 * DD)  g_q[gwarp - DD] = acc;
            else                      g_c = acc + b2[0];
        }
    }

    grid_barrier(base + NBLK);

    // ---- Phase B: eu_i = exp(-(z_i.p + c)), ev_i = exp(-(z_i.q)), s_i = eu_i*ev_i ----
    if (gwarp < NN) {
        const float4* pv = reinterpret_cast<const float4*>(g_p);
        const float4* qv = reinterpret_cast<const float4*>(g_q);
        float4 p0 = pv[lane], p1 = pv[lane + 32];
        float4 q0 = qv[lane], q1 = qv[lane + 32];
        float su = z0.x * p0.x;
        su = fmaf(z0.y, p0.y, su);
        su = fmaf(z0.z, p0.z, su);
        su = fmaf(z0.w, p0.w, su);
        su = fmaf(z1.x, p1.x, su);
        su = fmaf(z1.y, p1.y, su);
        su = fmaf(z1.z, p1.z, su);
        su = fmaf(z1.w, p1.w, su);
        float sv = z0.x * q0.x;
        sv = fmaf(z0.y, q0.y, sv);
        sv = fmaf(z0.z, q0.z, sv);
        sv = fmaf(z0.w, q0.w, sv);
        sv = fmaf(z1.x, q1.x, sv);
        sv = fmaf(z1.y, q1.y, sv);
        sv = fmaf(z1.z, q1.z, sv);
        sv = fmaf(z1.w, q1.w, sv);
        su = warp_reduce(su);
        sv = warp_reduce(sv);
        if (lane == 0) {
            float eu = __expf(-(su + g_c));
            float ev = __expf(-sv);
            g_eu[gwarp] = eu;
            g_ev[gwarp] = ev;
            g_s[gwarp]  = eu * ev;
        }
    }

    grid_barrier(base + 2u * NBLK);

    // ---- Phase C: adj[i,j] = (0.5*B + 0.5) / (B + s_i*s_j),
    //      B = 1 + eu_i*ev_j + eu_j*ev_i ----
    // Thread owns 4 CONTIGUOUS rows (rbase..rbase+3) x 1 float4 column group:
    // row-side values load as 3x LDG.128 instead of 12 scalar LDGs.
    const int colg    = threadIdx.x & 255;      // float4 column group 0..255
    const int row_sub = threadIdx.x >> 8;       // 0..1
    const int rbase   = blockIdx.x * 8 + row_sub * 4;
    const float4 euj = reinterpret_cast<const float4*>(g_eu)[colg];
    const float4 evj = reinterpret_cast<const float4*>(g_ev)[colg];
    const float4 sj  = reinterpret_cast<const float4*>(g_s)[colg];
    const float4 eur = *reinterpret_cast<const float4*>(g_eu + rbase);
    const float4 evr = *reinterpret_cast<const float4*>(g_ev + rbase);
    const float4 sr  = *reinterpret_cast<const float4*>(g_s  + rbase);
    const float eua[4] = {eur.x, eur.y, eur.z, eur.w};
    const float eva[4] = {evr.x, evr.y, evr.z, evr.w};
    const float sa[4]  = {sr.x,  sr.y,  sr.z,  sr.w};
#pragma unroll
    for (int rr = 0; rr < 4; rr++) {
        const int i = rbase + rr;
        const float eui = eua[rr];
        const float evi = eva[rr];
        const float si  = sa[rr];
        float4 o;
        {
            float B = fmaf(euj.x, evi, fmaf(eui, evj.x, 1.f));
            o.x = fmaf(0.5f, B, 0.5f) * frcp(fmaf(si, sj.x, B));
        }
        {
            float B = fmaf(euj.y, evi, fmaf(eui, evj.y, 1.f));
            o.y = fmaf(0.5f, B, 0.5f) * frcp(fmaf(si, sj.y, B));
        }
        {
            float B = fmaf(euj.z, evi, fmaf(eui, evj.z, 1.f));
            o.z = fmaf(0.5f, B, 0.5f) * frcp(fmaf(si, sj.z, B));
        }
        {
            float B = fmaf(euj.w, evi, fmaf(eui, evj.w, 1.f));
            o.w = fmaf(0.5f, B, 0.5f) * frcp(fmaf(si, sj.w, B));
        }
        st_cs_v4(reinterpret_cast<float4*>(out) + (size_t)i * (NN / 4) + colg, o);
    }

    // Advance epoch base for the next launch (causally after every CTA's entry
    // read of g_base, since barrier 2 has completed).
    if (blockIdx.x == 0 && threadIdx.x == 0) st_relaxed(&g_base, base + 2u * NBLK);
}

extern "C" void kernel_launch(void* const* d_in, const int* in_sizes, int n_in,
                              void* d_out, int out_size) {
    const float* z  = (const float*)d_in[0];  // [N, D]
    const float* w1 = (const float*)d_in[1];  // [2D, H]
    const float* b1 = (const float*)d_in[2];  // [H]
    const float* w2 = (const float*)d_in[3];  // [H]
    const float* b2 = (const float*)d_in[4];  // [1]
    float* out = (float*)d_out;               // [N, N]

    fused_decoder<<<NBLK, NTHR>>>(z, w1, b1, w2, b2, out);
}